// round 2
// baseline (speedup 1.0000x reference)
#include <cuda_runtime.h>

#define NROWS 4096      // B*T
#define VOCAB 32000
#define UNITS 64
#define GATES 256       // 4*UNITS
#define EMBED 512
#define TT 128
#define NB 32

// ---------------- device scratch (no allocations allowed) ----------------
__device__ float g_xz[NROWS * GATES];              // 4 MB
__device__ float g_hs[NROWS * UNITS];              // 1 MB
__device__ float g_feat[NROWS * 2 * UNITS];        // 2 MB
__device__ float g_elog[(size_t)NROWS * VOCAB];    // 524 MB (exp(logits))

// ---------------- packed f32x2 helpers (Blackwell) ----------------
__device__ __forceinline__ unsigned long long pack2(float x) {
    unsigned long long r;
    asm("mov.b64 %0, {%1, %2};" : "=l"(r) : "f"(x), "f"(x));
    return r;
}
__device__ __forceinline__ void ffma2(unsigned long long& d, unsigned long long a,
                                      unsigned long long b) {
    asm("fma.rn.f32x2 %0, %1, %2, %0;" : "+l"(d) : "l"(a), "l"(b));
}
__device__ __forceinline__ float2 unpack2(unsigned long long v) {
    float2 r;
    asm("mov.b64 {%0, %1}, %2;" : "=f"(r.x), "=f"(r.y) : "l"(v));
    return r;
}

// ---------------- kernel A: xz = emb[dec] @ Wx + b ----------------
__global__ __launch_bounds__(256) void k_xz(const int* __restrict__ dec,
                                            const float* __restrict__ emb,
                                            const float* __restrict__ Wx,
                                            const float* __restrict__ bvec) {
    __shared__ float xs[16 * EMBED];   // 32 KB
    __shared__ int tok[16];
    int tid = threadIdx.x;
    int rowBase = blockIdx.x * 16;
    if (tid < 16) tok[tid] = dec[rowBase + tid];
    __syncthreads();
    for (int i = tid; i < 16 * (EMBED / 4); i += 256) {
        int r = i >> 7, q = i & 127;
        ((float4*)xs)[r * (EMBED / 4) + q] =
            ((const float4*)(emb + (size_t)tok[r] * EMBED))[q];
    }
    __syncthreads();
    int g = tid;
    float bb = bvec[g];
    float acc[16];
#pragma unroll
    for (int r = 0; r < 16; r++) acc[r] = bb;
#pragma unroll 4
    for (int e = 0; e < EMBED; e++) {
        float w = Wx[e * GATES + g];
#pragma unroll
        for (int r = 0; r < 16; r++) acc[r] += xs[r * EMBED + e] * w;
    }
#pragma unroll
    for (int r = 0; r < 16; r++) g_xz[(size_t)(rowBase + r) * GATES + g] = acc[r];
}

// ---------------- kernel B: sequential LSTM ----------------
__global__ __launch_bounds__(256) void k_lstm(const float* __restrict__ h0,
                                              const float* __restrict__ c0,
                                              const float* __restrict__ Wh,
                                              float* __restrict__ tail) {
    int b = blockIdx.x;
    int g = threadIdx.x;
    float wh[UNITS];
#pragma unroll
    for (int u = 0; u < UNITS; u++) wh[u] = Wh[u * GATES + g];
    __shared__ float sh_h[UNITS];
    __shared__ float sh_z[GATES];
    float c = 0.f;
    if (g < UNITS) {
        sh_h[g] = h0[b * UNITS + g];
        c = c0[b * UNITS + g];
    }
    __syncthreads();
    for (int t = 0; t < TT; t++) {
        float z = g_xz[((size_t)b * TT + t) * GATES + g];
#pragma unroll
        for (int u = 0; u < UNITS; u++) z += sh_h[u] * wh[u];
        sh_z[g] = z;
        __syncthreads();
        if (g < UNITS) {
            float ig = 1.f / (1.f + expf(-sh_z[g]));
            float fg = 1.f / (1.f + expf(-sh_z[UNITS + g]));
            float gg = tanhf(sh_z[2 * UNITS + g]);
            float og = 1.f / (1.f + expf(-sh_z[3 * UNITS + g]));
            c = fg * c + ig * gg;
            float h = og * tanhf(c);
            sh_h[g] = h;
            g_hs[((size_t)b * TT + t) * UNITS + g] = h;
        }
        __syncthreads();
    }
    if (g < UNITS) {
        tail[b * UNITS + g] = sh_h[g];                    // hT
        tail[NB * UNITS + b * UNITS + g] = c;             // cT
    }
}

// ---------------- kernel C: Luong attention + feat assembly ----------------
__global__ __launch_bounds__(128) void k_attn(const float* __restrict__ enc,
                                              const float* __restrict__ h0) {
    __shared__ float q[UNITS];
    __shared__ float encp[TT * 65];
    __shared__ float red[TT];
    __shared__ float att[TT];
    int tid = threadIdx.x;
    int b = blockIdx.x >> 7;
    int t = blockIdx.x & 127;
    if (tid < UNITS)
        q[tid] = (t == 0) ? h0[b * UNITS + tid]
                          : g_hs[((size_t)b * TT + (t - 1)) * UNITS + tid];
    const float* eb = enc + (size_t)b * TT * UNITS;
    for (int i = tid; i < TT * UNITS; i += 128) {
        int s = i >> 6, u = i & 63;
        encp[s * 65 + u] = eb[i];
    }
    __syncthreads();
    float sc = 0.f;
    {
        const float* er = encp + tid * 65;
#pragma unroll
        for (int u = 0; u < UNITS; u++) sc += q[u] * er[u];
    }
    red[tid] = sc;
    __syncthreads();
    for (int st = 64; st > 0; st >>= 1) {
        if (tid < st) red[tid] = fmaxf(red[tid], red[tid + st]);
        __syncthreads();
    }
    float m = red[0];
    __syncthreads();
    float e = __expf(sc - m);
    red[tid] = e;
    __syncthreads();
    for (int st = 64; st > 0; st >>= 1) {
        if (tid < st) red[tid] += red[tid + st];
        __syncthreads();
    }
    att[tid] = e / red[0];
    __syncthreads();
    size_t row = blockIdx.x;   // b*TT + t
    if (tid < UNITS) {
        float acc = 0.f;
#pragma unroll 8
        for (int s = 0; s < TT; s++) acc += att[s] * encp[s * 65 + tid];
        g_feat[row * 128 + tid] = g_hs[row * UNITS + tid];  // seq half
        g_feat[row * 128 + UNITS + tid] = acc;              // ctx half
    }
}

// ---------------- kernel D1: elog = exp(feat @ Wd + bd) ----------------
// Logits bounded (|z| < ~12): exp without max-subtraction is safe; softmax is
// shift-invariant so the normalized result matches the reference.
#define LDA 132
#define GEMM_SMEM ((128 * LDA + 128 * 128) * 4)

__global__ __launch_bounds__(256) void k_gemm(const float* __restrict__ Wd,
                                              const float* __restrict__ bd) {
    extern __shared__ float smem[];
    float* As = smem;                  // 128 x LDA
    float* Bs = smem + 128 * LDA;      // 128 x 128
    int tid = threadIdx.x;
    int colBase = blockIdx.x * 128;
    int rowBase = blockIdx.y * 128;
    {
        int r0 = tid >> 5;             // 0..7
        int q4 = (tid & 31) * 4;
#pragma unroll
        for (int it = 0; it < 16; it++) {
            int r = it * 8 + r0;
            float4 v = *(const float4*)(g_feat + (size_t)(rowBase + r) * 128 + q4);
            *(float4*)(As + r * LDA + q4) = v;
        }
#pragma unroll
        for (int it = 0; it < 16; it++) {
            int k = it * 8 + r0;
            float4 v = *(const float4*)(Wd + (size_t)k * VOCAB + colBase + q4);
            *(float4*)(Bs + k * 128 + q4) = v;
        }
    }
    __syncthreads();
    int ty = tid >> 4, tx = tid & 15;
    unsigned long long acc[8][4];
#pragma unroll
    for (int i = 0; i < 8; i++)
#pragma unroll
        for (int j = 0; j < 4; j++) acc[i][j] = 0ull;

    const float* Ab = As + ty * 8 * LDA;
#pragma unroll 2
    for (int k0 = 0; k0 < 128; k0 += 4) {
        float4 a4[8];
#pragma unroll
        for (int i = 0; i < 8; i++) a4[i] = *(const float4*)(Ab + i * LDA + k0);
#pragma unroll
        for (int kk = 0; kk < 4; kk++) {
            unsigned long long bq[4];
#pragma unroll
            for (int j = 0; j < 4; j++)
                bq[j] = *(const unsigned long long*)(Bs + (k0 + kk) * 128 + tx * 2 + j * 32);
#pragma unroll
            for (int i = 0; i < 8; i++) {
                float av = (kk == 0) ? a4[i].x : (kk == 1) ? a4[i].y
                                    : (kk == 2) ? a4[i].z : a4[i].w;
                unsigned long long ap = pack2(av);
#pragma unroll
                for (int j = 0; j < 4; j++) ffma2(acc[i][j], ap, bq[j]);
            }
        }
    }
    // epilogue: exp(acc + bias), coalesced float2 stores (cols = 2*tx + 32*j)
    float2 bdv[4];
#pragma unroll
    for (int j = 0; j < 4; j++)
        bdv[j] = *(const float2*)(bd + colBase + tx * 2 + j * 32);
#pragma unroll
    for (int i = 0; i < 8; i++) {
        size_t row = (size_t)rowBase + ty * 8 + i;
        float* orow = g_elog + row * VOCAB + colBase;
#pragma unroll
        for (int j = 0; j < 4; j++) {
            float2 v = unpack2(acc[i][j]);
            v.x = __expf(v.x + bdv[j].x);
            v.y = __expf(v.y + bdv[j].y);
            *(float2*)(orow + tx * 2 + j * 32) = v;
        }
    }
}

// ---------------- kernel D2: normalize exp values (2 passes) ----------------
// 48KB smem throttles to 4 blocks/SM so pass 2 re-reads the row from L2.
__global__ __launch_bounds__(256) void k_softmax(float* __restrict__ out) {
    __shared__ float red[12288];   // 48 KB occupancy throttle
    int tid = threadIdx.x;
    size_t row = blockIdx.x;
    const float4* p = (const float4*)(g_elog + row * VOCAB);
    float4* o = (float4*)(out + row * VOCAB);
    float s = 0.f;
    for (int i = tid; i < VOCAB / 4; i += 256) {
        float4 v = p[i];
        s += (v.x + v.y) + (v.z + v.w);
    }
    red[tid] = s;
    __syncthreads();
    for (int st = 128; st > 0; st >>= 1) {
        if (tid < st) red[tid] += red[tid + st];
        __syncthreads();
    }
    float inv = 1.f / red[0];
    for (int i = tid; i < VOCAB / 4; i += 256) {
        float4 v = p[i];
        v.x *= inv; v.y *= inv; v.z *= inv; v.w *= inv;
        o[i] = v;
    }
}

// ---------------- launch ----------------
extern "C" void kernel_launch(void* const* d_in, const int* in_sizes, int n_in,
                              void* d_out, int out_size) {
    const float* enc = (const float*)d_in[0];   // [32,128,64]
    const int*   dec = (const int*)d_in[1];     // [32,128]
    const float* h0  = (const float*)d_in[2];   // [32,64]
    const float* c0  = (const float*)d_in[3];   // [32,64]
    const float* emb = (const float*)d_in[4];   // [32000,512]
    const float* Wx  = (const float*)d_in[5];   // [512,256]
    const float* Wh  = (const float*)d_in[6];   // [64,256]
    const float* bv  = (const float*)d_in[7];   // [256]
    const float* Wd  = (const float*)d_in[8];   // [128,32000]
    const float* bd  = (const float*)d_in[9];   // [32000]
    float* out = (float*)d_out;

    cudaFuncSetAttribute(k_gemm, cudaFuncAttributeMaxDynamicSharedMemorySize,
                         GEMM_SMEM);

    k_xz<<<256, 256>>>(dec, emb, Wx, bv);
    k_lstm<<<NB, 256>>>(h0, c0, Wh, out + (size_t)NROWS * VOCAB);
    k_attn<<<NROWS, 128>>>(enc, h0);
    k_gemm<<<dim3(VOCAB / 128, NROWS / 128), 256, GEMM_SMEM>>>(Wd, bd);
    k_softmax<<<NROWS, 256>>>(out);
}

// round 4
// speedup vs baseline: 1.1186x; 1.1186x over previous
#include <cuda_runtime.h>
#include <cstdint>

#define NROWS 4096      // B*T
#define VOCAB 32000
#define UNITS 64
#define GATES 256
#define EMBED 512
#define TT 128
#define NB 32

#define BM 128
#define BN 128
#define NT (VOCAB / BN)          // 250 col tiles
#define PADA 132                 // As row pad (u32): frag loads conflict-free
#define PADB 136                 // Bs row pad (u32): frag loads conflict-free

// ---------------- device scratch ----------------
__device__ __align__(256) float g_xz[NROWS * GATES];                  // 4 MB
__device__ __align__(256) float g_hs[NROWS * UNITS];                  // 1 MB
__device__ __align__(256) uint32_t g_featA[NROWS * 128];              // 2 MB (tf32)
__device__ __align__(256) uint32_t g_Wt[(size_t)128 * VOCAB];         // 16 MB (tf32)
__device__ __align__(256) float g_elog[(size_t)NROWS * VOCAB];        // 524 MB
__device__ __align__(256) float g_partial[(size_t)NT * NROWS];        // 4 MB
__device__ __align__(256) float g_inv[NROWS];

__device__ __forceinline__ uint32_t f2tf32(float x) {
    uint32_t r;
    asm("cvt.rna.tf32.f32 %0, %1;" : "=r"(r) : "f"(x));
    return r;
}

__device__ __forceinline__ void mma_tf32(float* c, const uint32_t* a,
                                         const uint32_t* b) {
    asm volatile(
        "mma.sync.aligned.m16n8k8.row.col.f32.tf32.tf32.f32 "
        "{%0,%1,%2,%3}, {%4,%5,%6,%7}, {%8,%9}, {%0,%1,%2,%3};"
        : "+f"(c[0]), "+f"(c[1]), "+f"(c[2]), "+f"(c[3])
        : "r"(a[0]), "r"(a[1]), "r"(a[2]), "r"(a[3]), "r"(b[0]), "r"(b[1]));
}

// ---------------- kernel: Wd f32 -> tf32 bits ----------------
__global__ __launch_bounds__(256) void k_cvtWd(const float* __restrict__ Wd) {
    size_t i = (size_t)blockIdx.x * 256 + threadIdx.x;   // float4 index
    const float4 v = ((const float4*)Wd)[i];
    uint4 r;
    r.x = f2tf32(v.x); r.y = f2tf32(v.y); r.z = f2tf32(v.z); r.w = f2tf32(v.w);
    ((uint4*)g_Wt)[i] = r;
}

// ---------------- kernel A: xz = emb[dec] @ Wx + b ----------------
__global__ __launch_bounds__(256) void k_xz(const int* __restrict__ dec,
                                            const float* __restrict__ emb,
                                            const float* __restrict__ Wx,
                                            const float* __restrict__ bvec) {
    __shared__ float xs[16 * EMBED];
    __shared__ int tok[16];
    int tid = threadIdx.x;
    int rowBase = blockIdx.x * 16;
    if (tid < 16) tok[tid] = dec[rowBase + tid];
    __syncthreads();
    for (int i = tid; i < 16 * (EMBED / 4); i += 256) {
        int r = i >> 7, q = i & 127;
        ((float4*)xs)[r * (EMBED / 4) + q] =
            ((const float4*)(emb + (size_t)tok[r] * EMBED))[q];
    }
    __syncthreads();
    int g = tid;
    float bb = bvec[g];
    float acc[16];
#pragma unroll
    for (int r = 0; r < 16; r++) acc[r] = bb;
#pragma unroll 4
    for (int e = 0; e < EMBED; e++) {
        float w = Wx[e * GATES + g];
#pragma unroll
        for (int r = 0; r < 16; r++) acc[r] += xs[r * EMBED + e] * w;
    }
#pragma unroll
    for (int r = 0; r < 16; r++) g_xz[(size_t)(rowBase + r) * GATES + g] = acc[r];
}

// ---------------- kernel B: sequential LSTM ----------------
__global__ __launch_bounds__(256) void k_lstm(const float* __restrict__ h0,
                                              const float* __restrict__ c0,
                                              const float* __restrict__ Wh,
                                              float* __restrict__ tail) {
    int b = blockIdx.x;
    int g = threadIdx.x;
    float wh[UNITS];
#pragma unroll
    for (int u = 0; u < UNITS; u++) wh[u] = Wh[u * GATES + g];
    __shared__ float sh_h[UNITS];
    __shared__ float sh_z[GATES];
    float c = 0.f;
    if (g < UNITS) {
        sh_h[g] = h0[b * UNITS + g];
        c = c0[b * UNITS + g];
    }
    __syncthreads();
    for (int t = 0; t < TT; t++) {
        float z = g_xz[((size_t)b * TT + t) * GATES + g];
#pragma unroll
        for (int u = 0; u < UNITS; u++) z += sh_h[u] * wh[u];
        sh_z[g] = z;
        __syncthreads();
        if (g < UNITS) {
            float ig = 1.f / (1.f + expf(-sh_z[g]));
            float fg = 1.f / (1.f + expf(-sh_z[UNITS + g]));
            float gg = tanhf(sh_z[2 * UNITS + g]);
            float og = 1.f / (1.f + expf(-sh_z[3 * UNITS + g]));
            c = fg * c + ig * gg;
            float h = og * tanhf(c);
            sh_h[g] = h;
            g_hs[((size_t)b * TT + t) * UNITS + g] = h;
        }
        __syncthreads();
    }
    if (g < UNITS) {
        tail[b * UNITS + g] = sh_h[g];
        tail[NB * UNITS + b * UNITS + g] = c;
    }
}

// ---------------- kernel C: attention + feat -> tf32 ----------------
__global__ __launch_bounds__(128) void k_attn(const float* __restrict__ enc,
                                              const float* __restrict__ h0) {
    __shared__ float q[UNITS];
    __shared__ float encp[TT * 65];
    __shared__ float red[TT];
    __shared__ float att[TT];
    int tid = threadIdx.x;
    int b = blockIdx.x >> 7;
    int t = blockIdx.x & 127;
    if (tid < UNITS)
        q[tid] = (t == 0) ? h0[b * UNITS + tid]
                          : g_hs[((size_t)b * TT + (t - 1)) * UNITS + tid];
    const float* eb = enc + (size_t)b * TT * UNITS;
    for (int i = tid; i < TT * UNITS; i += 128) {
        int s = i >> 6, u = i & 63;
        encp[s * 65 + u] = eb[i];
    }
    __syncthreads();
    float sc = 0.f;
    {
        const float* er = encp + tid * 65;
#pragma unroll
        for (int u = 0; u < UNITS; u++) sc += q[u] * er[u];
    }
    red[tid] = sc;
    __syncthreads();
    for (int st = 64; st > 0; st >>= 1) {
        if (tid < st) red[tid] = fmaxf(red[tid], red[tid + st]);
        __syncthreads();
    }
    float m = red[0];
    __syncthreads();
    float e = __expf(sc - m);
    red[tid] = e;
    __syncthreads();
    for (int st = 64; st > 0; st >>= 1) {
        if (tid < st) red[tid] += red[tid + st];
        __syncthreads();
    }
    att[tid] = e / red[0];
    __syncthreads();
    size_t row = blockIdx.x;
    if (tid < UNITS) {
        float ctx = 0.f;
#pragma unroll 8
        for (int s = 0; s < TT; s++) ctx += att[s] * encp[s * 65 + tid];
        g_featA[row * 128 + tid] = f2tf32(g_hs[row * UNITS + tid]);
        g_featA[row * 128 + UNITS + tid] = f2tf32(ctx);
    }
}

// ---------------- tf32 mma.sync GEMM + fused exp + row partials ----------------
// smem: As[128][132]u32 + Bs[128][136]u32 + srow[128] + sbd[128]
#define SMEM_AS (BM * PADA)
#define SMEM_BS (128 * PADB)
#define SMEM_MMA ((SMEM_AS + SMEM_BS + 256) * 4)

__global__ __launch_bounds__(256) void k_mma(const float* __restrict__ bd) {
    extern __shared__ uint32_t smem[];
    uint32_t* As = smem;
    uint32_t* Bs = smem + SMEM_AS;
    float* srow = (float*)(smem + SMEM_AS + SMEM_BS);
    float* sbd = srow + 128;

    int tid = threadIdx.x;
    int colBase = blockIdx.x * BN;
    int rowBase = blockIdx.y * BM;

    // loads: A tile (128 rows x 128 k, u32), B tile (128 k x 128 n, u32)
    for (int i = tid; i < 128 * 32; i += 256) {
        int m = i >> 5, q = (i & 31) * 4;
        *(uint4*)(As + m * PADA + q) =
            *(const uint4*)(g_featA + (size_t)(rowBase + m) * 128 + q);
    }
    for (int i = tid; i < 128 * 32; i += 256) {
        int k = i >> 5, q = (i & 31) * 4;
        *(uint4*)(Bs + k * PADB + q) =
            *(const uint4*)(g_Wt + (size_t)k * VOCAB + colBase + q);
    }
    if (tid < 128) {
        sbd[tid] = bd[colBase + tid];
        srow[tid] = 0.f;
    }
    __syncthreads();

    int lane = tid & 31, w = tid >> 5;
    int wr = w >> 2, wc = w & 3;            // 2 x 4 warp grid, 64x32 per warp
    int g = lane >> 2, t = lane & 3;

    float c[4][4][4];
#pragma unroll
    for (int i = 0; i < 4; i++)
#pragma unroll
        for (int j = 0; j < 4; j++)
#pragma unroll
            for (int k = 0; k < 4; k++) c[i][j][k] = 0.f;

    const uint32_t* Ab = As + (wr * 64 + g) * PADA + t;
    const uint32_t* Bb = Bs + t * PADB + wc * 32 + g;

#pragma unroll
    for (int k0 = 0; k0 < 128; k0 += 8) {
        uint32_t a[4][4];
#pragma unroll
        for (int i = 0; i < 4; i++) {
            const uint32_t* ap = Ab + i * 16 * PADA + k0;
            a[i][0] = ap[0];
            a[i][1] = ap[8 * PADA];
            a[i][2] = ap[4];
            a[i][3] = ap[8 * PADA + 4];
        }
        uint32_t b[4][2];
#pragma unroll
        for (int j = 0; j < 4; j++) {
            const uint32_t* bp = Bb + k0 * PADB + j * 8;
            b[j][0] = bp[0];
            b[j][1] = bp[4 * PADB];
        }
#pragma unroll
        for (int i = 0; i < 4; i++)
#pragma unroll
            for (int j = 0; j < 4; j++) mma_tf32(c[i][j], a[i], b[j]);
    }

    // epilogue: exp(logit + bd), store, accumulate row sums
    float rs[4][2];
#pragma unroll
    for (int i = 0; i < 4; i++) { rs[i][0] = 0.f; rs[i][1] = 0.f; }

#pragma unroll
    for (int i = 0; i < 4; i++) {
        int row0 = rowBase + wr * 64 + i * 16 + g;
#pragma unroll
        for (int j = 0; j < 4; j++) {
            int cl = wc * 32 + j * 8 + 2 * t;
            float b0 = sbd[cl], b1 = sbd[cl + 1];
            float e00 = __expf(c[i][j][0] + b0);
            float e01 = __expf(c[i][j][1] + b1);
            float e10 = __expf(c[i][j][2] + b0);
            float e11 = __expf(c[i][j][3] + b1);
            float2 v0 = {e00, e01}, v1 = {e10, e11};
            *(float2*)&g_elog[(size_t)row0 * VOCAB + colBase + cl] = v0;
            *(float2*)&g_elog[(size_t)(row0 + 8) * VOCAB + colBase + cl] = v1;
            rs[i][0] += e00 + e01;
            rs[i][1] += e10 + e11;
        }
    }
    // reduce over the 4 lanes of each group (they share rows)
#pragma unroll
    for (int i = 0; i < 4; i++) {
#pragma unroll
        for (int h = 0; h < 2; h++) {
            rs[i][h] += __shfl_xor_sync(0xffffffffu, rs[i][h], 1);
            rs[i][h] += __shfl_xor_sync(0xffffffffu, rs[i][h], 2);
        }
        if (t == 0) {
            atomicAdd(&srow[wr * 64 + i * 16 + g], rs[i][0]);
            atomicAdd(&srow[wr * 64 + i * 16 + g + 8], rs[i][1]);
        }
    }
    __syncthreads();
    if (tid < 128)
        g_partial[(size_t)blockIdx.x * NROWS + rowBase + tid] = srow[tid];
}

// ---------------- reduce partials -> 1/rowsum ----------------
__global__ __launch_bounds__(256) void k_rowsum() {
    int row = blockIdx.x * 256 + threadIdx.x;
    float s = 0.f;
    for (int j = 0; j < NT; j++) s += g_partial[(size_t)j * NROWS + row];
    g_inv[row] = 1.f / s;
}

// ---------------- normalize: out = elog * inv[row] ----------------
__global__ __launch_bounds__(256) void k_norm(float* __restrict__ out) {
    size_t row = blockIdx.x;
    float inv = g_inv[row];
    const float4* p = (const float4*)(g_elog + row * VOCAB);
    float4* o = (float4*)(out + row * VOCAB);
    for (int i = threadIdx.x; i < VOCAB / 4; i += 256) {
        float4 v = p[i];
        v.x *= inv; v.y *= inv; v.z *= inv; v.w *= inv;
        o[i] = v;
    }
}

// ---------------- launch ----------------
extern "C" void kernel_launch(void* const* d_in, const int* in_sizes, int n_in,
                              void* d_out, int out_size) {
    const float* enc = (const float*)d_in[0];
    const int*   dec = (const int*)d_in[1];
    const float* h0  = (const float*)d_in[2];
    const float* c0  = (const float*)d_in[3];
    const float* emb = (const float*)d_in[4];
    const float* Wx  = (const float*)d_in[5];
    const float* Wh  = (const float*)d_in[6];
    const float* bv  = (const float*)d_in[7];
    const float* Wd  = (const float*)d_in[8];
    const float* bd  = (const float*)d_in[9];
    float* out = (float*)d_out;

    cudaFuncSetAttribute(k_mma, cudaFuncAttributeMaxDynamicSharedMemorySize,
                         SMEM_MMA);

    k_cvtWd<<<(128 * VOCAB) / (4 * 256), 256>>>(Wd);
    k_xz<<<256, 256>>>(dec, emb, Wx, bv);
    k_lstm<<<NB, 256>>>(h0, c0, Wh, out + (size_t)NROWS * VOCAB);
    k_attn<<<NROWS, 128>>>(enc, h0);
    k_mma<<<dim3(NT, NROWS / BM), 256, SMEM_MMA>>>(bd);
    k_rowsum<<<NROWS / 256, 256>>>();
    k_norm<<<NROWS, 256>>>(out);
}

// round 5
// speedup vs baseline: 1.4182x; 1.2678x over previous
#include <cuda_runtime.h>
#include <cstdint>

#define NROWS 4096      // B*T
#define VOCAB 32000
#define UNITS 64
#define GATES 256
#define EMBED 512
#define TT 128
#define NB 32

#define BM 128
#define BN 128
#define KC 32                    // k-chunk
#define NKC 4                    // 128 / 32
#define NT (VOCAB / BN)          // 250 col tiles
#define PADA 36                  // As row pad (u32): (4g+t) mod 32 bijective
#define PADB 136                 // Bs row pad (u32): (8t+g) mod 32 bijective

// smem layout (u32 indices)
#define AS_N (BM * PADA)         // 4608
#define BS_N (KC * PADB)         // 4352
#define OFF_AS0 0
#define OFF_AS1 AS_N
#define OFF_BS0 (2 * AS_N)
#define OFF_BS1 (2 * AS_N + BS_N)
#define OFF_SROW (2 * AS_N + 2 * BS_N)
#define OFF_SBD (OFF_SROW + 128)
#define SMEM_MMA ((OFF_SBD + 128) * 4)

// ---------------- device scratch ----------------
__device__ __align__(256) float g_xz[NROWS * GATES];
__device__ __align__(256) float g_hs[NROWS * UNITS];
__device__ __align__(256) uint32_t g_featA[NROWS * 128];        // tf32
__device__ __align__(256) uint32_t g_Wt[(size_t)128 * VOCAB];   // tf32
__device__ __align__(256) float g_partial[(size_t)NT * NROWS];
__device__ __align__(256) float g_inv[NROWS];

__device__ __forceinline__ uint32_t f2tf32(float x) {
    uint32_t r;
    asm("cvt.rna.tf32.f32 %0, %1;" : "=r"(r) : "f"(x));
    return r;
}
__device__ __forceinline__ void mma_tf32(float* c, const uint32_t* a,
                                         const uint32_t* b) {
    asm volatile(
        "mma.sync.aligned.m16n8k8.row.col.f32.tf32.tf32.f32 "
        "{%0,%1,%2,%3}, {%4,%5,%6,%7}, {%8,%9}, {%0,%1,%2,%3};"
        : "+f"(c[0]), "+f"(c[1]), "+f"(c[2]), "+f"(c[3])
        : "r"(a[0]), "r"(a[1]), "r"(a[2]), "r"(a[3]), "r"(b[0]), "r"(b[1]));
}
__device__ __forceinline__ uint32_t smem_u32(const void* p) {
    uint32_t a;
    asm("{ .reg .u64 t; cvta.to.shared.u64 t, %1; cvt.u32.u64 %0, t; }"
        : "=r"(a) : "l"(p));
    return a;
}
__device__ __forceinline__ void cp16(uint32_t dst, const void* src) {
    asm volatile("cp.async.ca.shared.global [%0], [%1], 16;"
                 :: "r"(dst), "l"(src) : "memory");
}
#define CP_COMMIT() asm volatile("cp.async.commit_group;" ::: "memory")
#define CP_WAIT(n)  asm volatile("cp.async.wait_group %0;" :: "n"(n) : "memory")

// ---------------- kernel: Wd f32 -> tf32 bits ----------------
__global__ __launch_bounds__(256) void k_cvtWd(const float* __restrict__ Wd) {
    size_t i = (size_t)blockIdx.x * 256 + threadIdx.x;
    const float4 v = ((const float4*)Wd)[i];
    uint4 r;
    r.x = f2tf32(v.x); r.y = f2tf32(v.y); r.z = f2tf32(v.z); r.w = f2tf32(v.w);
    ((uint4*)g_Wt)[i] = r;
}

// ---------------- kernel A: xz = emb[dec] @ Wx + b ----------------
__global__ __launch_bounds__(256) void k_xz(const int* __restrict__ dec,
                                            const float* __restrict__ emb,
                                            const float* __restrict__ Wx,
                                            const float* __restrict__ bvec) {
    __shared__ float xs[16 * EMBED];
    __shared__ int tok[16];
    int tid = threadIdx.x;
    int rowBase = blockIdx.x * 16;
    if (tid < 16) tok[tid] = dec[rowBase + tid];
    __syncthreads();
    for (int i = tid; i < 16 * (EMBED / 4); i += 256) {
        int r = i >> 7, q = i & 127;
        ((float4*)xs)[r * (EMBED / 4) + q] =
            ((const float4*)(emb + (size_t)tok[r] * EMBED))[q];
    }
    __syncthreads();
    int g = tid;
    float bb = bvec[g];
    float acc[16];
#pragma unroll
    for (int r = 0; r < 16; r++) acc[r] = bb;
#pragma unroll 4
    for (int e = 0; e < EMBED; e++) {
        float w = Wx[e * GATES + g];
#pragma unroll
        for (int r = 0; r < 16; r++) acc[r] += xs[r * EMBED + e] * w;
    }
#pragma unroll
    for (int r = 0; r < 16; r++) g_xz[(size_t)(rowBase + r) * GATES + g] = acc[r];
}

// ---------------- kernel B: sequential LSTM ----------------
__global__ __launch_bounds__(256) void k_lstm(const float* __restrict__ h0,
                                              const float* __restrict__ c0,
                                              const float* __restrict__ Wh,
                                              float* __restrict__ tail) {
    int b = blockIdx.x;
    int g = threadIdx.x;
    float wh[UNITS];
#pragma unroll
    for (int u = 0; u < UNITS; u++) wh[u] = Wh[u * GATES + g];
    __shared__ float sh_h[UNITS];
    __shared__ float sh_z[GATES];
    float c = 0.f;
    if (g < UNITS) {
        sh_h[g] = h0[b * UNITS + g];
        c = c0[b * UNITS + g];
    }
    __syncthreads();
    for (int t = 0; t < TT; t++) {
        float z = g_xz[((size_t)b * TT + t) * GATES + g];
#pragma unroll
        for (int u = 0; u < UNITS; u++) z += sh_h[u] * wh[u];
        sh_z[g] = z;
        __syncthreads();
        if (g < UNITS) {
            float ig = 1.f / (1.f + expf(-sh_z[g]));
            float fg = 1.f / (1.f + expf(-sh_z[UNITS + g]));
            float gg = tanhf(sh_z[2 * UNITS + g]);
            float og = 1.f / (1.f + expf(-sh_z[3 * UNITS + g]));
            c = fg * c + ig * gg;
            float h = og * tanhf(c);
            sh_h[g] = h;
            g_hs[((size_t)b * TT + t) * UNITS + g] = h;
        }
        __syncthreads();
    }
    if (g < UNITS) {
        tail[b * UNITS + g] = sh_h[g];
        tail[NB * UNITS + b * UNITS + g] = c;
    }
}

// ---------------- kernel C: attention + feat -> tf32 ----------------
__global__ __launch_bounds__(128) void k_attn(const float* __restrict__ enc,
                                              const float* __restrict__ h0) {
    __shared__ float q[UNITS];
    __shared__ float encp[TT * 65];
    __shared__ float red[TT];
    __shared__ float att[TT];
    int tid = threadIdx.x;
    int b = blockIdx.x >> 7;
    int t = blockIdx.x & 127;
    if (tid < UNITS)
        q[tid] = (t == 0) ? h0[b * UNITS + tid]
                          : g_hs[((size_t)b * TT + (t - 1)) * UNITS + tid];
    const float* eb = enc + (size_t)b * TT * UNITS;
    for (int i = tid; i < TT * UNITS; i += 128) {
        int s = i >> 6, u = i & 63;
        encp[s * 65 + u] = eb[i];
    }
    __syncthreads();
    float sc = 0.f;
    {
        const float* er = encp + tid * 65;
#pragma unroll
        for (int u = 0; u < UNITS; u++) sc += q[u] * er[u];
    }
    red[tid] = sc;
    __syncthreads();
    for (int st = 64; st > 0; st >>= 1) {
        if (tid < st) red[tid] = fmaxf(red[tid], red[tid + st]);
        __syncthreads();
    }
    float m = red[0];
    __syncthreads();
    float e = __expf(sc - m);
    red[tid] = e;
    __syncthreads();
    for (int st = 64; st > 0; st >>= 1) {
        if (tid < st) red[tid] += red[tid + st];
        __syncthreads();
    }
    att[tid] = e / red[0];
    __syncthreads();
    size_t row = blockIdx.x;
    if (tid < UNITS) {
        float ctx = 0.f;
#pragma unroll 8
        for (int s = 0; s < TT; s++) ctx += att[s] * encp[s * 65 + tid];
        g_featA[row * 128 + tid] = f2tf32(g_hs[row * UNITS + tid]);
        g_featA[row * 128 + UNITS + tid] = f2tf32(ctx);
    }
}

// ---------------- pipelined tf32 GEMM, run twice ----------------
// pass 1: partial row sums of exp(logit+bd).  pass 2: out = exp * inv[row].
__device__ __forceinline__ void load_chunk(uint32_t asA, uint32_t asB,
                                           const uint32_t* gA,
                                           const uint32_t* gB, int c, int tid) {
#pragma unroll
    for (int it = 0; it < 4; it++) {          // A: 128 rows x 8 16B-chunks
        int idx = tid + it * 256;
        int row = idx >> 3, q = (idx & 7) * 4;
        cp16(asA + (row * PADA + q) * 4, gA + (size_t)row * 128 + c * KC + q);
    }
#pragma unroll
    for (int it = 0; it < 4; it++) {          // B: 32 k x 32 16B-chunks
        int idx = tid + it * 256;
        int k = idx >> 5, q = (idx & 31) * 4;
        cp16(asB + (k * PADB + q) * 4, gB + (size_t)(c * KC + k) * VOCAB + q);
    }
    CP_COMMIT();
}

__global__ __launch_bounds__(256) void k_mma(const float* __restrict__ bd,
                                             float* __restrict__ out, int pass) {
    extern __shared__ uint32_t smem[];
    uint32_t sb = smem_u32(smem);
    float* srow = (float*)(smem + OFF_SROW);
    float* sbd = (float*)(smem + OFF_SBD);

    int tid = threadIdx.x;
    int colBase = blockIdx.x * BN;
    int rowBase = blockIdx.y * BM;
    const uint32_t* gA = g_featA + (size_t)rowBase * 128;
    const uint32_t* gB = g_Wt + colBase;

    if (tid < 128) {
        sbd[tid] = bd[colBase + tid];
        srow[tid] = 0.f;
    }
    load_chunk(sb + OFF_AS0 * 4, sb + OFF_BS0 * 4, gA, gB, 0, tid);

    int lane = tid & 31, w = tid >> 5;
    int wr = w >> 2, wc = w & 3;             // 2 x 4 warps, 64x32 tiles
    int g = lane >> 2, t = lane & 3;

    float c[4][4][4];
#pragma unroll
    for (int i = 0; i < 4; i++)
#pragma unroll
        for (int j = 0; j < 4; j++)
#pragma unroll
            for (int k = 0; k < 4; k++) c[i][j][k] = 0.f;

#pragma unroll
    for (int ch = 0; ch < NKC; ch++) {
        if (ch + 1 < NKC)
            load_chunk(sb + ((ch & 1) ? OFF_AS0 : OFF_AS1) * 4,
                       sb + ((ch & 1) ? OFF_BS0 : OFF_BS1) * 4,
                       gA, gB, ch + 1, tid);
        if (ch + 1 < NKC) CP_WAIT(1); else CP_WAIT(0);
        __syncthreads();

        const uint32_t* As = smem + ((ch & 1) ? OFF_AS1 : OFF_AS0);
        const uint32_t* Bs = smem + ((ch & 1) ? OFF_BS1 : OFF_BS0);
        const uint32_t* Ab = As + (wr * 64 + g) * PADA + t;
        const uint32_t* Bb = Bs + t * PADB + wc * 32 + g;
#pragma unroll
        for (int k0 = 0; k0 < KC; k0 += 8) {
            uint32_t a[4][4];
#pragma unroll
            for (int i = 0; i < 4; i++) {
                const uint32_t* ap = Ab + i * 16 * PADA + k0;
                a[i][0] = ap[0];
                a[i][1] = ap[8 * PADA];
                a[i][2] = ap[4];
                a[i][3] = ap[8 * PADA + 4];
            }
            uint32_t b[4][2];
#pragma unroll
            for (int j = 0; j < 4; j++) {
                const uint32_t* bp = Bb + k0 * PADB + j * 8;
                b[j][0] = bp[0];
                b[j][1] = bp[4 * PADB];
            }
#pragma unroll
            for (int i = 0; i < 4; i++)
#pragma unroll
                for (int j = 0; j < 4; j++) mma_tf32(c[i][j], a[i], b[j]);
        }
        __syncthreads();
    }

    if (pass == 1) {
        float rs[4][2];
#pragma unroll
        for (int i = 0; i < 4; i++) { rs[i][0] = 0.f; rs[i][1] = 0.f; }
#pragma unroll
        for (int i = 0; i < 4; i++)
#pragma unroll
            for (int j = 0; j < 4; j++) {
                int cl = wc * 32 + j * 8 + 2 * t;
                float b0 = sbd[cl], b1 = sbd[cl + 1];
                rs[i][0] += __expf(c[i][j][0] + b0) + __expf(c[i][j][1] + b1);
                rs[i][1] += __expf(c[i][j][2] + b0) + __expf(c[i][j][3] + b1);
            }
#pragma unroll
        for (int i = 0; i < 4; i++) {
#pragma unroll
            for (int h = 0; h < 2; h++) {
                rs[i][h] += __shfl_xor_sync(0xffffffffu, rs[i][h], 1);
                rs[i][h] += __shfl_xor_sync(0xffffffffu, rs[i][h], 2);
            }
            if (t == 0) {
                atomicAdd(&srow[wr * 64 + i * 16 + g], rs[i][0]);
                atomicAdd(&srow[wr * 64 + i * 16 + g + 8], rs[i][1]);
            }
        }
        __syncthreads();
        if (tid < 128)
            g_partial[(size_t)blockIdx.x * NROWS + rowBase + tid] = srow[tid];
    } else {
        float inv0[4], inv1[4];
#pragma unroll
        for (int i = 0; i < 4; i++) {
            int r = rowBase + wr * 64 + i * 16 + g;
            inv0[i] = g_inv[r];
            inv1[i] = g_inv[r + 8];
        }
#pragma unroll
        for (int i = 0; i < 4; i++) {
            int row0 = rowBase + wr * 64 + i * 16 + g;
#pragma unroll
            for (int j = 0; j < 4; j++) {
                int cl = wc * 32 + j * 8 + 2 * t;
                float b0 = sbd[cl], b1 = sbd[cl + 1];
                float2 v0 = {__expf(c[i][j][0] + b0) * inv0[i],
                             __expf(c[i][j][1] + b1) * inv0[i]};
                float2 v1 = {__expf(c[i][j][2] + b0) * inv1[i],
                             __expf(c[i][j][3] + b1) * inv1[i]};
                *(float2*)&out[(size_t)row0 * VOCAB + colBase + cl] = v0;
                *(float2*)&out[(size_t)(row0 + 8) * VOCAB + colBase + cl] = v1;
            }
        }
    }
}

// ---------------- reduce partials -> 1/rowsum ----------------
__global__ __launch_bounds__(256) void k_rowsum() {
    int row = blockIdx.x * 256 + threadIdx.x;
    float s = 0.f;
    for (int j = 0; j < NT; j++) s += g_partial[(size_t)j * NROWS + row];
    g_inv[row] = 1.f / s;
}

// ---------------- launch ----------------
extern "C" void kernel_launch(void* const* d_in, const int* in_sizes, int n_in,
                              void* d_out, int out_size) {
    const float* enc = (const float*)d_in[0];
    const int*   dec = (const int*)d_in[1];
    const float* h0  = (const float*)d_in[2];
    const float* c0  = (const float*)d_in[3];
    const float* emb = (const float*)d_in[4];
    const float* Wx  = (const float*)d_in[5];
    const float* Wh  = (const float*)d_in[6];
    const float* bv  = (const float*)d_in[7];
    const float* Wd  = (const float*)d_in[8];
    const float* bd  = (const float*)d_in[9];
    float* out = (float*)d_out;

    cudaFuncSetAttribute(k_mma, cudaFuncAttributeMaxDynamicSharedMemorySize,
                         SMEM_MMA);

    k_cvtWd<<<(128 * VOCAB) / (4 * 256), 256>>>(Wd);
    k_xz<<<256, 256>>>(dec, emb, Wx, bv);
    k_lstm<<<NB, 256>>>(h0, c0, Wh, out + (size_t)NROWS * VOCAB);
    k_attn<<<NROWS, 128>>>(enc, h0);
    k_mma<<<dim3(NT, NROWS / BM), 256, SMEM_MMA>>>(bd, out, 1);
    k_rowsum<<<NROWS / 256, 256>>>();
    k_mma<<<dim3(NT, NROWS / BM), 256, SMEM_MMA>>>(bd, out, 2);
}

// round 6
// speedup vs baseline: 2.1051x; 1.4844x over previous
#include <cuda_runtime.h>
#include <cuda_fp16.h>
#include <cstdint>

#define NROWS 4096      // B*T
#define VOCAB 32000
#define UNITS 64
#define GATES 256
#define EMBED 512
#define TT 128
#define NB 32

#define BM 128
#define BN 128
#define NT (VOCAB / BN)          // 250 col tiles
#define PADK 136                 // halves per row (k=128 + 8 pad): conflict-free

// smem (halves): As 128x136, Bs 128x136, then srow/sbd floats
#define AS_H (BM * PADK)         // 17408
#define BS_H (BN * PADK)         // 17408
#define SMEM_MMA (AS_H * 2 + BS_H * 2 + 256 * 4 + 16)

// ---------------- device scratch ----------------
__device__ __align__(256) float g_xz[NROWS * GATES];
__device__ __align__(256) float g_hs[NROWS * UNITS];
__device__ __align__(256) __half g_Ah[NROWS * 128];            // feat fp16
__device__ __align__(256) __half g_Wh[(size_t)VOCAB * 128];    // Wd^T fp16
__device__ __align__(256) float g_partial[(size_t)NT * NROWS];
__device__ __align__(256) float g_inv[NROWS];

__device__ __forceinline__ void mma_f16(float* c, const uint32_t* a,
                                        const uint32_t* b) {
    asm volatile(
        "mma.sync.aligned.m16n8k16.row.col.f32.f16.f16.f32 "
        "{%0,%1,%2,%3}, {%4,%5,%6,%7}, {%8,%9}, {%0,%1,%2,%3};"
        : "+f"(c[0]), "+f"(c[1]), "+f"(c[2]), "+f"(c[3])
        : "r"(a[0]), "r"(a[1]), "r"(a[2]), "r"(a[3]), "r"(b[0]), "r"(b[1]));
}
__device__ __forceinline__ uint32_t smem_u32(const void* p) {
    uint32_t a;
    asm("{ .reg .u64 t; cvta.to.shared.u64 t, %1; cvt.u32.u64 %0, t; }"
        : "=r"(a) : "l"(p));
    return a;
}
__device__ __forceinline__ void cp16(uint32_t dst, const void* src) {
    asm volatile("cp.async.ca.shared.global [%0], [%1], 16;"
                 :: "r"(dst), "l"(src) : "memory");
}
#define CP_COMMIT() asm volatile("cp.async.commit_group;" ::: "memory")
#define CP_WAIT0()  asm volatile("cp.async.wait_group 0;" ::: "memory")

// ---------------- kernel: Wd [128][32000] f32 -> g_Wh [32000][128] fp16 ----
__global__ __launch_bounds__(256) void k_cvtWd(const float* __restrict__ Wd) {
    __shared__ float sm[32][33];
    int tx = threadIdx.x & 31, ty = threadIdx.x >> 5;   // 32 x 8
    int v0 = blockIdx.x * 32, k0 = blockIdx.y * 32;
#pragma unroll
    for (int i = 0; i < 4; i++) {
        int k = ty + i * 8;
        sm[k][tx] = Wd[(size_t)(k0 + k) * VOCAB + v0 + tx];
    }
    __syncthreads();
#pragma unroll
    for (int i = 0; i < 4; i++) {
        int vl = ty + i * 8;
        g_Wh[(size_t)(v0 + vl) * 128 + k0 + tx] = __float2half(sm[tx][vl]);
    }
}

// ---------------- kernel A: xz = emb[dec] @ Wx + b ----------------
__global__ __launch_bounds__(256) void k_xz(const int* __restrict__ dec,
                                            const float* __restrict__ emb,
                                            const float* __restrict__ Wx,
                                            const float* __restrict__ bvec) {
    __shared__ float xs[16 * EMBED];
    __shared__ int tok[16];
    int tid = threadIdx.x;
    int rowBase = blockIdx.x * 16;
    if (tid < 16) tok[tid] = dec[rowBase + tid];
    __syncthreads();
    for (int i = tid; i < 16 * (EMBED / 4); i += 256) {
        int r = i >> 7, q = i & 127;
        ((float4*)xs)[r * (EMBED / 4) + q] =
            ((const float4*)(emb + (size_t)tok[r] * EMBED))[q];
    }
    __syncthreads();
    int g = tid;
    float bb = bvec[g];
    float acc[16];
#pragma unroll
    for (int r = 0; r < 16; r++) acc[r] = bb;
#pragma unroll 4
    for (int e = 0; e < EMBED; e++) {
        float w = Wx[e * GATES + g];
#pragma unroll
        for (int r = 0; r < 16; r++) acc[r] += xs[r * EMBED + e] * w;
    }
#pragma unroll
    for (int r = 0; r < 16; r++) g_xz[(size_t)(rowBase + r) * GATES + g] = acc[r];
}

// ---------------- kernel B: sequential LSTM ----------------
__global__ __launch_bounds__(256) void k_lstm(const float* __restrict__ h0,
                                              const float* __restrict__ c0,
                                              const float* __restrict__ Wh,
                                              float* __restrict__ tail) {
    int b = blockIdx.x;
    int g = threadIdx.x;
    float wh[UNITS];
#pragma unroll
    for (int u = 0; u < UNITS; u++) wh[u] = Wh[u * GATES + g];
    __shared__ float sh_h[UNITS];
    __shared__ float sh_z[GATES];
    float c = 0.f;
    if (g < UNITS) {
        sh_h[g] = h0[b * UNITS + g];
        c = c0[b * UNITS + g];
    }
    __syncthreads();
    for (int t = 0; t < TT; t++) {
        float z = g_xz[((size_t)b * TT + t) * GATES + g];
#pragma unroll
        for (int u = 0; u < UNITS; u++) z += sh_h[u] * wh[u];
        sh_z[g] = z;
        __syncthreads();
        if (g < UNITS) {
            float ig = 1.f / (1.f + expf(-sh_z[g]));
            float fg = 1.f / (1.f + expf(-sh_z[UNITS + g]));
            float gg = tanhf(sh_z[2 * UNITS + g]);
            float og = 1.f / (1.f + expf(-sh_z[3 * UNITS + g]));
            c = fg * c + ig * gg;
            float h = og * tanhf(c);
            sh_h[g] = h;
            g_hs[((size_t)b * TT + t) * UNITS + g] = h;
        }
        __syncthreads();
    }
    if (g < UNITS) {
        tail[b * UNITS + g] = sh_h[g];
        tail[NB * UNITS + b * UNITS + g] = c;
    }
}

// ---------------- kernel C: attention + feat -> fp16 ----------------
__global__ __launch_bounds__(128) void k_attn(const float* __restrict__ enc,
                                              const float* __restrict__ h0) {
    __shared__ float q[UNITS];
    __shared__ float encp[TT * 65];
    __shared__ float red[TT];
    __shared__ float att[TT];
    int tid = threadIdx.x;
    int b = blockIdx.x >> 7;
    int t = blockIdx.x & 127;
    if (tid < UNITS)
        q[tid] = (t == 0) ? h0[b * UNITS + tid]
                          : g_hs[((size_t)b * TT + (t - 1)) * UNITS + tid];
    const float* eb = enc + (size_t)b * TT * UNITS;
    for (int i = tid; i < TT * UNITS; i += 128) {
        int s = i >> 6, u = i & 63;
        encp[s * 65 + u] = eb[i];
    }
    __syncthreads();
    float sc = 0.f;
    {
        const float* er = encp + tid * 65;
#pragma unroll
        for (int u = 0; u < UNITS; u++) sc += q[u] * er[u];
    }
    red[tid] = sc;
    __syncthreads();
    for (int st = 64; st > 0; st >>= 1) {
        if (tid < st) red[tid] = fmaxf(red[tid], red[tid + st]);
        __syncthreads();
    }
    float m = red[0];
    __syncthreads();
    float e = __expf(sc - m);
    red[tid] = e;
    __syncthreads();
    for (int st = 64; st > 0; st >>= 1) {
        if (tid < st) red[tid] += red[tid + st];
        __syncthreads();
    }
    att[tid] = e / red[0];
    __syncthreads();
    size_t row = blockIdx.x;
    if (tid < UNITS) {
        float ctx = 0.f;
#pragma unroll 8
        for (int s = 0; s < TT; s++) ctx += att[s] * encp[s * 65 + tid];
        g_Ah[row * 128 + tid] = __float2half(g_hs[row * UNITS + tid]);
        g_Ah[row * 128 + UNITS + tid] = __float2half(ctx);
    }
}

// ---------------- fp16 m16n8k16 GEMM, run twice ----------------
// pass 1: partial row sums of exp(logit+bd).  pass 2: out = exp * inv[row].
__global__ __launch_bounds__(256, 2) void k_mma(const float* __restrict__ bd,
                                                float* __restrict__ out,
                                                int pass) {
    extern __shared__ __half hsm[];
    __half* As = hsm;                  // [128][PADK]
    __half* Bs = hsm + AS_H;           // [128][PADK] (n-major)
    float* srow = (float*)(hsm + AS_H + BS_H);
    float* sbd = srow + 128;
    uint32_t sb = smem_u32(hsm);

    int tid = threadIdx.x;
    int colBase = blockIdx.x * BN;
    int rowBase = blockIdx.y * BM;

    // load tiles: 128 rows x 16 16B-chunks each, for A and B
    {
        const __half* gA = g_Ah + (size_t)rowBase * 128;
        const __half* gB = g_Wh + (size_t)colBase * 128;
#pragma unroll
        for (int it = 0; it < 8; it++) {
            int idx = tid + it * 256;
            int r = idx >> 4, cqb = (idx & 15) * 16;   // byte offset in row
            cp16(sb + r * (PADK * 2) + cqb, (const char*)gA + (size_t)r * 256 + cqb);
        }
#pragma unroll
        for (int it = 0; it < 8; it++) {
            int idx = tid + it * 256;
            int r = idx >> 4, cqb = (idx & 15) * 16;
            cp16(sb + AS_H * 2 + r * (PADK * 2) + cqb,
                 (const char*)gB + (size_t)r * 256 + cqb);
        }
        CP_COMMIT();
    }
    if (tid < 128) {
        sbd[tid] = bd[colBase + tid];
        srow[tid] = 0.f;
    }
    CP_WAIT0();
    __syncthreads();

    int lane = tid & 31, w = tid >> 5;
    int wr = w >> 2, wc = w & 3;             // 2 x 4 warps, 64x32 tiles
    int g = lane >> 2, t = lane & 3;

    float c[4][4][4];
#pragma unroll
    for (int i = 0; i < 4; i++)
#pragma unroll
        for (int j = 0; j < 4; j++)
#pragma unroll
            for (int k = 0; k < 4; k++) c[i][j][k] = 0.f;

    const __half* Ab = As + (wr * 64 + g) * PADK + 2 * t;
    const __half* Bb = Bs + (wc * 32 + g) * PADK + 2 * t;

#pragma unroll
    for (int k0 = 0; k0 < 128; k0 += 16) {
        uint32_t a[4][4];
#pragma unroll
        for (int i = 0; i < 4; i++) {
            const __half* ap = Ab + i * 16 * PADK + k0;
            a[i][0] = *(const uint32_t*)(ap);
            a[i][1] = *(const uint32_t*)(ap + 8 * PADK);
            a[i][2] = *(const uint32_t*)(ap + 8);
            a[i][3] = *(const uint32_t*)(ap + 8 * PADK + 8);
        }
        uint32_t b[4][2];
#pragma unroll
        for (int j = 0; j < 4; j++) {
            const __half* bp = Bb + j * 8 * PADK + k0;
            b[j][0] = *(const uint32_t*)(bp);
            b[j][1] = *(const uint32_t*)(bp + 8);
        }
#pragma unroll
        for (int i = 0; i < 4; i++)
#pragma unroll
            for (int j = 0; j < 4; j++) mma_f16(c[i][j], a[i], b[j]);
    }
    __syncthreads();

    if (pass == 1) {
        float rs[4][2];
#pragma unroll
        for (int i = 0; i < 4; i++) { rs[i][0] = 0.f; rs[i][1] = 0.f; }
#pragma unroll
        for (int i = 0; i < 4; i++)
#pragma unroll
            for (int j = 0; j < 4; j++) {
                int cl = wc * 32 + j * 8 + 2 * t;
                float b0 = sbd[cl], b1 = sbd[cl + 1];
                rs[i][0] += __expf(c[i][j][0] + b0) + __expf(c[i][j][1] + b1);
                rs[i][1] += __expf(c[i][j][2] + b0) + __expf(c[i][j][3] + b1);
            }
#pragma unroll
        for (int i = 0; i < 4; i++) {
#pragma unroll
            for (int h = 0; h < 2; h++) {
                rs[i][h] += __shfl_xor_sync(0xffffffffu, rs[i][h], 1);
                rs[i][h] += __shfl_xor_sync(0xffffffffu, rs[i][h], 2);
            }
            if (t == 0) {
                atomicAdd(&srow[wr * 64 + i * 16 + g], rs[i][0]);
                atomicAdd(&srow[wr * 64 + i * 16 + g + 8], rs[i][1]);
            }
        }
        __syncthreads();
        if (tid < 128)
            g_partial[(size_t)blockIdx.x * NROWS + rowBase + tid] = srow[tid];
    } else {
        float inv0[4], inv1[4];
#pragma unroll
        for (int i = 0; i < 4; i++) {
            int r = rowBase + wr * 64 + i * 16 + g;
            inv0[i] = g_inv[r];
            inv1[i] = g_inv[r + 8];
        }
#pragma unroll
        for (int i = 0; i < 4; i++) {
            int row0 = rowBase + wr * 64 + i * 16 + g;
#pragma unroll
            for (int j = 0; j < 4; j++) {
                int cl = wc * 32 + j * 8 + 2 * t;
                float b0 = sbd[cl], b1 = sbd[cl + 1];
                float2 v0 = {__expf(c[i][j][0] + b0) * inv0[i],
                             __expf(c[i][j][1] + b1) * inv0[i]};
                float2 v1 = {__expf(c[i][j][2] + b0) * inv1[i],
                             __expf(c[i][j][3] + b1) * inv1[i]};
                *(float2*)&out[(size_t)row0 * VOCAB + colBase + cl] = v0;
                *(float2*)&out[(size_t)(row0 + 8) * VOCAB + colBase + cl] = v1;
            }
        }
    }
}

// ---------------- reduce partials -> 1/rowsum ----------------
__global__ __launch_bounds__(256) void k_rowsum() {
    int row = blockIdx.x * 256 + threadIdx.x;
    float s = 0.f;
    for (int j = 0; j < NT; j++) s += g_partial[(size_t)j * NROWS + row];
    g_inv[row] = 1.f / s;
}

// ---------------- launch ----------------
extern "C" void kernel_launch(void* const* d_in, const int* in_sizes, int n_in,
                              void* d_out, int out_size) {
    const float* enc = (const float*)d_in[0];
    const int*   dec = (const int*)d_in[1];
    const float* h0  = (const float*)d_in[2];
    const float* c0  = (const float*)d_in[3];
    const float* emb = (const float*)d_in[4];
    const float* Wx  = (const float*)d_in[5];
    const float* Wh  = (const float*)d_in[6];
    const float* bv  = (const float*)d_in[7];
    const float* Wd  = (const float*)d_in[8];
    const float* bd  = (const float*)d_in[9];
    float* out = (float*)d_out;

    cudaFuncSetAttribute(k_mma, cudaFuncAttributeMaxDynamicSharedMemorySize,
                         SMEM_MMA);

    k_cvtWd<<<dim3(VOCAB / 32, 4), 256>>>(Wd);
    k_xz<<<256, 256>>>(dec, emb, Wx, bv);
    k_lstm<<<NB, 256>>>(h0, c0, Wh, out + (size_t)NROWS * VOCAB);
    k_attn<<<NROWS, 128>>>(enc, h0);
    k_mma<<<dim3(NT, NROWS / BM), 256, SMEM_MMA>>>(bd, out, 1);
    k_rowsum<<<NROWS / 256, 256>>>();
    k_mma<<<dim3(NT, NROWS / BM), 256, SMEM_MMA>>>(bd, out, 2);
}

// round 7
// speedup vs baseline: 2.1954x; 1.0429x over previous
#include <cuda_runtime.h>
#include <cuda_fp16.h>
#include <cstdint>

#define NROWS 4096      // B*T
#define VOCAB 32000
#define UNITS 64
#define GATES 256
#define EMBED 512
#define TT 128
#define NB 32

#define BM 128
#define BN 128
#define NT (VOCAB / BN)          // 250 col tiles
#define PADK 136                 // halves per row (272B = 17*16B: ldmatrix-clean)

#define AS_H (BM * PADK)
#define BS_H (BN * PADK)
#define SMEM_MMA (AS_H * 2 + BS_H * 2 + 256 * 4 + 16)

// ---------------- device scratch ----------------
__device__ __align__(256) float g_xz[NROWS * GATES];
__device__ __align__(256) float g_hs[NROWS * UNITS];
__device__ __align__(256) __half g_Ah[NROWS * 128];            // feat fp16
__device__ __align__(256) __half g_Wh[(size_t)VOCAB * 128];    // Wd^T fp16
__device__ __align__(256) float g_partial[(size_t)NT * NROWS];
__device__ __align__(256) float g_inv[NROWS];

__device__ __forceinline__ void mma_f16(float* c, const uint32_t* a,
                                        const uint32_t* b) {
    asm volatile(
        "mma.sync.aligned.m16n8k16.row.col.f32.f16.f16.f32 "
        "{%0,%1,%2,%3}, {%4,%5,%6,%7}, {%8,%9}, {%0,%1,%2,%3};"
        : "+f"(c[0]), "+f"(c[1]), "+f"(c[2]), "+f"(c[3])
        : "r"(a[0]), "r"(a[1]), "r"(a[2]), "r"(a[3]), "r"(b[0]), "r"(b[1]));
}
__device__ __forceinline__ void ldm_x4(uint32_t* r, uint32_t addr) {
    asm volatile("ldmatrix.sync.aligned.m8n8.x4.shared.b16 {%0,%1,%2,%3}, [%4];"
                 : "=r"(r[0]), "=r"(r[1]), "=r"(r[2]), "=r"(r[3]) : "r"(addr));
}
__device__ __forceinline__ uint32_t smem_u32(const void* p) {
    uint32_t a;
    asm("{ .reg .u64 t; cvta.to.shared.u64 t, %1; cvt.u32.u64 %0, t; }"
        : "=r"(a) : "l"(p));
    return a;
}
__device__ __forceinline__ void cp16(uint32_t dst, const void* src) {
    asm volatile("cp.async.ca.shared.global [%0], [%1], 16;"
                 :: "r"(dst), "l"(src) : "memory");
}
#define CP_COMMIT() asm volatile("cp.async.commit_group;" ::: "memory")
#define CP_WAIT0()  asm volatile("cp.async.wait_group 0;" ::: "memory")

// ---------------- kernel: Wd [128][32000] f32 -> g_Wh [32000][128] fp16 ----
__global__ __launch_bounds__(256) void k_cvtWd(const float* __restrict__ Wd) {
    __shared__ float sm[32][33];
    int tx = threadIdx.x & 31, ty = threadIdx.x >> 5;
    int v0 = blockIdx.x * 32, k0 = blockIdx.y * 32;
#pragma unroll
    for (int i = 0; i < 4; i++) {
        int k = ty + i * 8;
        sm[k][tx] = Wd[(size_t)(k0 + k) * VOCAB + v0 + tx];
    }
    __syncthreads();
#pragma unroll
    for (int i = 0; i < 4; i++) {
        int vl = ty + i * 8;
        g_Wh[(size_t)(v0 + vl) * 128 + k0 + tx] = __float2half(sm[tx][vl]);
    }
}

// ---------------- kernel A: xz = emb[dec] @ Wx + b ----------------
__global__ __launch_bounds__(256) void k_xz(const int* __restrict__ dec,
                                            const float* __restrict__ emb,
                                            const float* __restrict__ Wx,
                                            const float* __restrict__ bvec) {
    __shared__ float xs[16 * EMBED];
    __shared__ int tok[16];
    int tid = threadIdx.x;
    int rowBase = blockIdx.x * 16;
    if (tid < 16) tok[tid] = dec[rowBase + tid];
    __syncthreads();
    for (int i = tid; i < 16 * (EMBED / 4); i += 256) {
        int r = i >> 7, q = i & 127;
        ((float4*)xs)[r * (EMBED / 4) + q] =
            ((const float4*)(emb + (size_t)tok[r] * EMBED))[q];
    }
    __syncthreads();
    int g = tid;
    float bb = bvec[g];
    float acc[16];
#pragma unroll
    for (int r = 0; r < 16; r++) acc[r] = bb;
#pragma unroll 4
    for (int e = 0; e < EMBED; e++) {
        float w = Wx[e * GATES + g];
#pragma unroll
        for (int r = 0; r < 16; r++) acc[r] += xs[r * EMBED + e] * w;
    }
#pragma unroll
    for (int r = 0; r < 16; r++) g_xz[(size_t)(rowBase + r) * GATES + g] = acc[r];
}

// ---------------- kernel B: sequential LSTM ----------------
__global__ __launch_bounds__(256) void k_lstm(const float* __restrict__ h0,
                                              const float* __restrict__ c0,
                                              const float* __restrict__ Wh,
                                              float* __restrict__ tail) {
    int b = blockIdx.x;
    int g = threadIdx.x;
    float wh[UNITS];
#pragma unroll
    for (int u = 0; u < UNITS; u++) wh[u] = Wh[u * GATES + g];
    __shared__ __align__(16) float sh_h[UNITS];
    __shared__ float sh_z[GATES];
    float c = 0.f;
    if (g < UNITS) {
        sh_h[g] = h0[b * UNITS + g];
        c = c0[b * UNITS + g];
    }
    __syncthreads();
    for (int t = 0; t < TT; t++) {
        float z = g_xz[((size_t)b * TT + t) * GATES + g];
#pragma unroll
        for (int u4 = 0; u4 < UNITS / 4; u4++) {
            float4 h4 = ((const float4*)sh_h)[u4];
            z += h4.x * wh[u4 * 4] + h4.y * wh[u4 * 4 + 1] +
                 h4.z * wh[u4 * 4 + 2] + h4.w * wh[u4 * 4 + 3];
        }
        sh_z[g] = z;
        __syncthreads();
        if (g < UNITS) {
            float ig = 1.f / (1.f + expf(-sh_z[g]));
            float fg = 1.f / (1.f + expf(-sh_z[UNITS + g]));
            float gg = tanhf(sh_z[2 * UNITS + g]);
            float og = 1.f / (1.f + expf(-sh_z[3 * UNITS + g]));
            c = fg * c + ig * gg;
            float h = og * tanhf(c);
            sh_h[g] = h;
            g_hs[((size_t)b * TT + t) * UNITS + g] = h;
        }
        __syncthreads();
    }
    if (g < UNITS) {
        tail[b * UNITS + g] = sh_h[g];
        tail[NB * UNITS + b * UNITS + g] = c;
    }
}

// ---------------- kernel C: attention (per-b 16-t chunks) -> fp16 feat ----
__global__ __launch_bounds__(256) void k_attn(const float* __restrict__ enc,
                                              const float* __restrict__ h0) {
    __shared__ float encp[TT * 65];     // 33 KB
    __shared__ float qs[16 * 64];       // 4 KB
    __shared__ float att[16 * 128];     // 8 KB
    int tid = threadIdx.x;
    int b = blockIdx.y, tc = blockIdx.x;
    const float* eb = enc + (size_t)b * TT * UNITS;
    for (int i = tid; i < TT * UNITS; i += 256) {
        int s = i >> 6, u = i & 63;
        encp[s * 65 + u] = eb[i];
    }
    for (int i = tid; i < 16 * 64; i += 256) {
        int tl = i >> 6, u = i & 63;
        int t = tc * 16 + tl;
        qs[i] = (t == 0) ? h0[b * 64 + u]
                         : g_hs[((size_t)b * TT + t - 1) * 64 + u];
    }
    __syncthreads();
    int w = tid >> 5, lane = tid & 31;
#pragma unroll
    for (int tt = 0; tt < 2; tt++) {
        int tl = w * 2 + tt;
        const float* q = qs + tl * 64;
        float sc[4];
#pragma unroll
        for (int k = 0; k < 4; k++) {
            const float* er = encp + (lane + k * 32) * 65;
            float acc = 0.f;
#pragma unroll
            for (int u = 0; u < 64; u++) acc += q[u] * er[u];
            sc[k] = acc;
        }
        float m = fmaxf(fmaxf(sc[0], sc[1]), fmaxf(sc[2], sc[3]));
#pragma unroll
        for (int st = 16; st; st >>= 1)
            m = fmaxf(m, __shfl_xor_sync(0xffffffffu, m, st));
        float sum = 0.f;
#pragma unroll
        for (int k = 0; k < 4; k++) { sc[k] = __expf(sc[k] - m); sum += sc[k]; }
#pragma unroll
        for (int st = 16; st; st >>= 1)
            sum += __shfl_xor_sync(0xffffffffu, sum, st);
        float inv = 1.f / sum;
#pragma unroll
        for (int k = 0; k < 4; k++) att[tl * 128 + lane + k * 32] = sc[k] * inv;
    }
    __syncwarp();
#pragma unroll
    for (int tt = 0; tt < 2; tt++) {
        int tl = w * 2 + tt;
        size_t row = (size_t)b * TT + tc * 16 + tl;
        const float* at = att + tl * 128;
#pragma unroll
        for (int h = 0; h < 2; h++) {
            int u = lane + h * 32;
            float acc = 0.f;
#pragma unroll
            for (int s = 0; s < 128; s++) acc += at[s] * encp[s * 65 + u];
            g_Ah[row * 128 + UNITS + u] = __float2half(acc);
            g_Ah[row * 128 + u] = __float2half(g_hs[row * UNITS + u]);
        }
    }
}

// ---------------- fp16 m16n8k16 GEMM (ldmatrix), run twice ----------------
__global__ __launch_bounds__(256, 2) void k_mma(const float* __restrict__ bd,
                                                float* __restrict__ out,
                                                int pass) {
    extern __shared__ __half hsm[];
    float* srow = (float*)(hsm + AS_H + BS_H);
    float* sbd = srow + 128;
    uint32_t sb = smem_u32(hsm);

    int tid = threadIdx.x;
    int colBase = blockIdx.x * BN;
    int rowBase = blockIdx.y * BM;

    {
        const __half* gA = g_Ah + (size_t)rowBase * 128;
        const __half* gB = g_Wh + (size_t)colBase * 128;
#pragma unroll
        for (int it = 0; it < 8; it++) {
            int idx = tid + it * 256;
            int r = idx >> 4, cqb = (idx & 15) * 16;
            cp16(sb + r * (PADK * 2) + cqb, (const char*)gA + (size_t)r * 256 + cqb);
        }
#pragma unroll
        for (int it = 0; it < 8; it++) {
            int idx = tid + it * 256;
            int r = idx >> 4, cqb = (idx & 15) * 16;
            cp16(sb + AS_H * 2 + r * (PADK * 2) + cqb,
                 (const char*)gB + (size_t)r * 256 + cqb);
        }
        CP_COMMIT();
    }
    if (tid < 128) {
        sbd[tid] = bd[colBase + tid];
        srow[tid] = 0.f;
    }
    CP_WAIT0();
    __syncthreads();

    int lane = tid & 31, w = tid >> 5;
    int wr = w >> 2, wc = w & 3;             // 2 x 4 warps, 64x32 tiles
    int g = lane >> 2, t = lane & 3;
    int mq = lane >> 3, rq = lane & 7;       // ldmatrix address lanes

    uint32_t aAddr[4];
#pragma unroll
    for (int i = 0; i < 4; i++)
        aAddr[i] = sb + (((wr * 64 + i * 16 + (mq & 1) * 8 + rq) * PADK) +
                         (mq >> 1) * 8) * 2;
    uint32_t bAddr0 = sb + AS_H * 2 +
                      (((wc * 32 + (mq >> 1) * 8 + rq) * PADK) + (mq & 1) * 8) * 2;
    uint32_t bAddr1 = bAddr0 + 16 * PADK * 2;

    float c[4][4][4];
#pragma unroll
    for (int i = 0; i < 4; i++)
#pragma unroll
        for (int j = 0; j < 4; j++)
#pragma unroll
            for (int k = 0; k < 4; k++) c[i][j][k] = 0.f;

#pragma unroll
    for (int k0 = 0; k0 < 8; k0++) {
        uint32_t a[4][4], bb[8];
#pragma unroll
        for (int i = 0; i < 4; i++) ldm_x4(a[i], aAddr[i] + k0 * 32);
        ldm_x4(bb, bAddr0 + k0 * 32);
        ldm_x4(bb + 4, bAddr1 + k0 * 32);
#pragma unroll
        for (int i = 0; i < 4; i++)
#pragma unroll
            for (int j = 0; j < 4; j++) mma_f16(c[i][j], a[i], bb + j * 2);
    }
    __syncthreads();

    if (pass == 1) {
        float rs[4][2];
#pragma unroll
        for (int i = 0; i < 4; i++) { rs[i][0] = 0.f; rs[i][1] = 0.f; }
#pragma unroll
        for (int i = 0; i < 4; i++)
#pragma unroll
            for (int j = 0; j < 4; j++) {
                int cl = wc * 32 + j * 8 + 2 * t;
                float b0 = sbd[cl], b1 = sbd[cl + 1];
                rs[i][0] += __expf(c[i][j][0] + b0) + __expf(c[i][j][1] + b1);
                rs[i][1] += __expf(c[i][j][2] + b0) + __expf(c[i][j][3] + b1);
            }
#pragma unroll
        for (int i = 0; i < 4; i++) {
#pragma unroll
            for (int h = 0; h < 2; h++) {
                rs[i][h] += __shfl_xor_sync(0xffffffffu, rs[i][h], 1);
                rs[i][h] += __shfl_xor_sync(0xffffffffu, rs[i][h], 2);
            }
            if (t == 0) {
                atomicAdd(&srow[wr * 64 + i * 16 + g], rs[i][0]);
                atomicAdd(&srow[wr * 64 + i * 16 + g + 8], rs[i][1]);
            }
        }
        __syncthreads();
        if (tid < 128)
            g_partial[(size_t)blockIdx.x * NROWS + rowBase + tid] = srow[tid];
    } else {
        float inv0[4], inv1[4];
#pragma unroll
        for (int i = 0; i < 4; i++) {
            int r = rowBase + wr * 64 + i * 16 + g;
            inv0[i] = g_inv[r];
            inv1[i] = g_inv[r + 8];
        }
#pragma unroll
        for (int i = 0; i < 4; i++) {
            int row0 = rowBase + wr * 64 + i * 16 + g;
#pragma unroll
            for (int j = 0; j < 4; j++) {
                int cl = wc * 32 + j * 8 + 2 * t;
                float b0 = sbd[cl], b1 = sbd[cl + 1];
                float2 v0 = {__expf(c[i][j][0] + b0) * inv0[i],
                             __expf(c[i][j][1] + b1) * inv0[i]};
                float2 v1 = {__expf(c[i][j][2] + b0) * inv1[i],
                             __expf(c[i][j][3] + b1) * inv1[i]};
                *(float2*)&out[(size_t)row0 * VOCAB + colBase + cl] = v0;
                *(float2*)&out[(size_t)(row0 + 8) * VOCAB + colBase + cl] = v1;
            }
        }
    }
}

// ---------------- reduce partials -> 1/rowsum ----------------
__global__ __launch_bounds__(256) void k_rowsum() {
    int row = blockIdx.x * 256 + threadIdx.x;
    float s = 0.f;
    for (int j = 0; j < NT; j++) s += g_partial[(size_t)j * NROWS + row];
    g_inv[row] = 1.f / s;
}

// ---------------- launch ----------------
extern "C" void kernel_launch(void* const* d_in, const int* in_sizes, int n_in,
                              void* d_out, int out_size) {
    const float* enc = (const float*)d_in[0];
    const int*   dec = (const int*)d_in[1];
    const float* h0  = (const float*)d_in[2];
    const float* c0  = (const float*)d_in[3];
    const float* emb = (const float*)d_in[4];
    const float* Wx  = (const float*)d_in[5];
    const float* Wh  = (const float*)d_in[6];
    const float* bv  = (const float*)d_in[7];
    const float* Wd  = (const float*)d_in[8];
    const float* bd  = (const float*)d_in[9];
    float* out = (float*)d_out;

    cudaFuncSetAttribute(k_mma, cudaFuncAttributeMaxDynamicSharedMemorySize,
                         SMEM_MMA);

    k_cvtWd<<<dim3(VOCAB / 32, 4), 256>>>(Wd);
    k_xz<<<256, 256>>>(dec, emb, Wx, bv);
    k_lstm<<<NB, 256>>>(h0, c0, Wh, out + (size_t)NROWS * VOCAB);
    k_attn<<<dim3(TT / 16, NB), 256>>>(enc, h0);
    k_mma<<<dim3(NT, NROWS / BM), 256, SMEM_MMA>>>(bd, out, 1);
    k_rowsum<<<NROWS / 256, 256>>>();
    k_mma<<<dim3(NT, NROWS / BM), 256, SMEM_MMA>>>(bd, out, 2);
}

// round 10
// speedup vs baseline: 2.2273x; 1.0145x over previous
#include <cuda_runtime.h>
#include <cuda_fp16.h>
#include <cstdint>

#define NROWS 4096      // B*T
#define VOCAB 32000
#define UNITS 64
#define GATES 256
#define EMBED 512
#define TT 128
#define NB 32

#define BM 128
#define BN 128
#define NT (VOCAB / BN)          // 250 col tiles
#define PADK 136

#define AS_H (BM * PADK)
#define BS_H (BN * PADK)
#define SMEM_MMA (AS_H * 2 + BS_H * 2 + 256 * 4 + 16)

// ---------------- device scratch ----------------
__device__ __align__(256) float g_xz[NROWS * GATES];
__device__ __align__(256) float g_hs[NROWS * UNITS];
__device__ __align__(256) __half g_Ah[NROWS * 128];            // feat fp16
__device__ __align__(256) __half g_Wh[(size_t)VOCAB * 128];    // Wd^T fp16
__device__ __align__(256) __half g_eh[(size_t)NROWS * VOCAB];  // exp fp16, 262 MB
__device__ __align__(256) float g_partial[(size_t)NT * NROWS];
__device__ __align__(256) float g_inv[NROWS];

__device__ __forceinline__ void mma_f16(float* c, const uint32_t* a,
                                        const uint32_t* b) {
    asm volatile(
        "mma.sync.aligned.m16n8k16.row.col.f32.f16.f16.f32 "
        "{%0,%1,%2,%3}, {%4,%5,%6,%7}, {%8,%9}, {%0,%1,%2,%3};"
        : "+f"(c[0]), "+f"(c[1]), "+f"(c[2]), "+f"(c[3])
        : "r"(a[0]), "r"(a[1]), "r"(a[2]), "r"(a[3]), "r"(b[0]), "r"(b[1]));
}
__device__ __forceinline__ void ldm_x4(uint32_t* r, uint32_t addr) {
    asm volatile("ldmatrix.sync.aligned.m8n8.x4.shared.b16 {%0,%1,%2,%3}, [%4];"
                 : "=r"(r[0]), "=r"(r[1]), "=r"(r[2]), "=r"(r[3]) : "r"(addr));
}
__device__ __forceinline__ uint32_t smem_u32(const void* p) {
    uint32_t a;
    asm("{ .reg .u64 t; cvta.to.shared.u64 t, %1; cvt.u32.u64 %0, t; }"
        : "=r"(a) : "l"(p));
    return a;
}
__device__ __forceinline__ void cp16(uint32_t dst, const void* src) {
    asm volatile("cp.async.ca.shared.global [%0], [%1], 16;"
                 :: "r"(dst), "l"(src) : "memory");
}
#define CP_COMMIT() asm volatile("cp.async.commit_group;" ::: "memory")
#define CP_WAIT0()  asm volatile("cp.async.wait_group 0;" ::: "memory")

// ---------------- kernel: Wd [128][32000] f32 -> g_Wh [32000][128] fp16 ----
__global__ __launch_bounds__(256) void k_cvtWd(const float* __restrict__ Wd) {
    __shared__ float sm[32][33];
    int tx = threadIdx.x & 31, ty = threadIdx.x >> 5;
    int v0 = blockIdx.x * 32, k0 = blockIdx.y * 32;
#pragma unroll
    for (int i = 0; i < 4; i++) {
        int k = ty + i * 8;
        sm[k][tx] = Wd[(size_t)(k0 + k) * VOCAB + v0 + tx];
    }
    __syncthreads();
#pragma unroll
    for (int i = 0; i < 4; i++) {
        int vl = ty + i * 8;
        g_Wh[(size_t)(v0 + vl) * 128 + k0 + tx] = __float2half(sm[tx][vl]);
    }
}

// ---------------- kernel A: xz = emb[dec] @ Wx + b ----------------
__global__ __launch_bounds__(256) void k_xz(const int* __restrict__ dec,
                                            const float* __restrict__ emb,
                                            const float* __restrict__ Wx,
                                            const float* __restrict__ bvec) {
    __shared__ float xs[16 * EMBED];
    __shared__ int tok[16];
    int tid = threadIdx.x;
    int rowBase = blockIdx.x * 16;
    if (tid < 16) tok[tid] = dec[rowBase + tid];
    __syncthreads();
    for (int i = tid; i < 16 * (EMBED / 4); i += 256) {
        int r = i >> 7, q = i & 127;
        ((float4*)xs)[r * (EMBED / 4) + q] =
            ((const float4*)(emb + (size_t)tok[r] * EMBED))[q];
    }
    __syncthreads();
    int g = tid;
    float bb = bvec[g];
    float acc[16];
#pragma unroll
    for (int r = 0; r < 16; r++) acc[r] = bb;
#pragma unroll 4
    for (int e = 0; e < EMBED; e++) {
        float w = Wx[e * GATES + g];
#pragma unroll
        for (int r = 0; r < 16; r++) acc[r] += xs[r * EMBED + e] * w;
    }
#pragma unroll
    for (int r = 0; r < 16; r++) g_xz[(size_t)(rowBase + r) * GATES + g] = acc[r];
}

// ---------------- kernel B: sequential LSTM ----------------
__global__ __launch_bounds__(256) void k_lstm(const float* __restrict__ h0,
                                              const float* __restrict__ c0,
                                              const float* __restrict__ Wh,
                                              float* __restrict__ tail) {
    int b = blockIdx.x;
    int g = threadIdx.x;
    float wh[UNITS];
#pragma unroll
    for (int u = 0; u < UNITS; u++) wh[u] = Wh[u * GATES + g];
    __shared__ __align__(16) float sh_h[UNITS];
    __shared__ float sh_z[GATES];
    float c = 0.f;
    if (g < UNITS) {
        sh_h[g] = h0[b * UNITS + g];
        c = c0[b * UNITS + g];
    }
    __syncthreads();
    for (int t = 0; t < TT; t++) {
        float z = g_xz[((size_t)b * TT + t) * GATES + g];
#pragma unroll
        for (int u4 = 0; u4 < UNITS / 4; u4++) {
            float4 h4 = ((const float4*)sh_h)[u4];
            z += h4.x * wh[u4 * 4] + h4.y * wh[u4 * 4 + 1] +
                 h4.z * wh[u4 * 4 + 2] + h4.w * wh[u4 * 4 + 3];
        }
        sh_z[g] = z;
        __syncthreads();
        if (g < UNITS) {
            float ig = 1.f / (1.f + expf(-sh_z[g]));
            float fg = 1.f / (1.f + expf(-sh_z[UNITS + g]));
            float gg = tanhf(sh_z[2 * UNITS + g]);
            float og = 1.f / (1.f + expf(-sh_z[3 * UNITS + g]));
            c = fg * c + ig * gg;
            float h = og * tanhf(c);
            sh_h[g] = h;
            g_hs[((size_t)b * TT + t) * UNITS + g] = h;
        }
        __syncthreads();
    }
    if (g < UNITS) {
        tail[b * UNITS + g] = sh_h[g];
        tail[NB * UNITS + b * UNITS + g] = c;
    }
}

// ---------------- kernel C: attention (per-b 16-t chunks) -> fp16 feat ----
__global__ __launch_bounds__(256) void k_attn(const float* __restrict__ enc,
                                              const float* __restrict__ h0) {
    __shared__ float encp[TT * 65];
    __shared__ float qs[16 * 64];
    __shared__ float att[16 * 128];
    int tid = threadIdx.x;
    int b = blockIdx.y, tc = blockIdx.x;
    const float* eb = enc + (size_t)b * TT * UNITS;
    for (int i = tid; i < TT * UNITS; i += 256) {
        int s = i >> 6, u = i & 63;
        encp[s * 65 + u] = eb[i];
    }
    for (int i = tid; i < 16 * 64; i += 256) {
        int tl = i >> 6, u = i & 63;
        int t = tc * 16 + tl;
        qs[i] = (t == 0) ? h0[b * 64 + u]
                         : g_hs[((size_t)b * TT + t - 1) * 64 + u];
    }
    __syncthreads();
    int w = tid >> 5, lane = tid & 31;
#pragma unroll 1
    for (int tt = 0; tt < 2; tt++) {
        int tl = w * 2 + tt;
        const float* q = qs + tl * 64;
        float sc[4];
#pragma unroll
        for (int k = 0; k < 4; k++) {
            const float* er = encp + (lane + k * 32) * 65;
            float acc = 0.f;
#pragma unroll 16
            for (int u = 0; u < 64; u++) acc += q[u] * er[u];
            sc[k] = acc;
        }
        float m = fmaxf(fmaxf(sc[0], sc[1]), fmaxf(sc[2], sc[3]));
#pragma unroll
        for (int st = 16; st; st >>= 1)
            m = fmaxf(m, __shfl_xor_sync(0xffffffffu, m, st));
        float sum = 0.f;
#pragma unroll
        for (int k = 0; k < 4; k++) { sc[k] = __expf(sc[k] - m); sum += sc[k]; }
#pragma unroll
        for (int st = 16; st; st >>= 1)
            sum += __shfl_xor_sync(0xffffffffu, sum, st);
        float inv = 1.f / sum;
#pragma unroll
        for (int k = 0; k < 4; k++) att[tl * 128 + lane + k * 32] = sc[k] * inv;
    }
    __syncwarp();
#pragma unroll 1
    for (int tt = 0; tt < 2; tt++) {
        int tl = w * 2 + tt;
        size_t row = (size_t)b * TT + tc * 16 + tl;
        const float* at = att + tl * 128;
#pragma unroll 1
        for (int h = 0; h < 2; h++) {
            int u = lane + h * 32;
            float acc = 0.f;
#pragma unroll 16
            for (int s = 0; s < 128; s++) acc += at[s] * encp[s * 65 + u];
            g_Ah[row * 128 + UNITS + u] = __float2half(acc);
            g_Ah[row * 128 + u] = __float2half(g_hs[row * UNITS + u]);
        }
    }
}

// ---------------- fp16 m16n8k16 GEMM, single pass ----------------
// writes exp(logit+bd) as fp16 to g_eh + per-tile row-sum partials.
__global__ __launch_bounds__(256, 2) void k_mma(const float* __restrict__ bd) {
    extern __shared__ __half hsm[];
    float* srow = (float*)(hsm + AS_H + BS_H);
    float* sbd = srow + 128;
    uint32_t sb = smem_u32(hsm);

    int tid = threadIdx.x;
    int colBase = blockIdx.x * BN;
    int rowBase = blockIdx.y * BM;

    {
        const __half* gA = g_Ah + (size_t)rowBase * 128;
        const __half* gB = g_Wh + (size_t)colBase * 128;
#pragma unroll
        for (int it = 0; it < 8; it++) {
            int idx = tid + it * 256;
            int r = idx >> 4, cqb = (idx & 15) * 16;
            cp16(sb + r * (PADK * 2) + cqb, (const char*)gA + (size_t)r * 256 + cqb);
        }
#pragma unroll
        for (int it = 0; it < 8; it++) {
            int idx = tid + it * 256;
            int r = idx >> 4, cqb = (idx & 15) * 16;
            cp16(sb + AS_H * 2 + r * (PADK * 2) + cqb,
                 (const char*)gB + (size_t)r * 256 + cqb);
        }
        CP_COMMIT();
    }
    if (tid < 128) {
        sbd[tid] = bd[colBase + tid];
        srow[tid] = 0.f;
    }
    CP_WAIT0();
    __syncthreads();

    int lane = tid & 31, w = tid >> 5;
    int wr = w >> 2, wc = w & 3;
    int g = lane >> 2, t = lane & 3;
    int mq = lane >> 3, rq = lane & 7;

    uint32_t aAddr[4];
#pragma unroll
    for (int i = 0; i < 4; i++)
        aAddr[i] = sb + (((wr * 64 + i * 16 + (mq & 1) * 8 + rq) * PADK) +
                         (mq >> 1) * 8) * 2;
    uint32_t bAddr0 = sb + AS_H * 2 +
                      (((wc * 32 + (mq >> 1) * 8 + rq) * PADK) + (mq & 1) * 8) * 2;
    uint32_t bAddr1 = bAddr0 + 16 * PADK * 2;

    float c[4][4][4];
#pragma unroll
    for (int i = 0; i < 4; i++)
#pragma unroll
        for (int j = 0; j < 4; j++)
#pragma unroll
            for (int k = 0; k < 4; k++) c[i][j][k] = 0.f;

#pragma unroll
    for (int k0 = 0; k0 < 8; k0++) {
        uint32_t a[4][4], bb[8];
#pragma unroll
        for (int i = 0; i < 4; i++) ldm_x4(a[i], aAddr[i] + k0 * 32);
        ldm_x4(bb, bAddr0 + k0 * 32);
        ldm_x4(bb + 4, bAddr1 + k0 * 32);
#pragma unroll
        for (int i = 0; i < 4; i++)
#pragma unroll
            for (int j = 0; j < 4; j++) mma_f16(c[i][j], a[i], bb + j * 2);
    }
    __syncthreads();

    float rs[4][2];
#pragma unroll
    for (int i = 0; i < 4; i++) { rs[i][0] = 0.f; rs[i][1] = 0.f; }
#pragma unroll
    for (int i = 0; i < 4; i++) {
        int row0 = rowBase + wr * 64 + i * 16 + g;
#pragma unroll
        for (int j = 0; j < 4; j++) {
            int cl = wc * 32 + j * 8 + 2 * t;
            float b0 = sbd[cl], b1 = sbd[cl + 1];
            float e00 = __expf(c[i][j][0] + b0);
            float e01 = __expf(c[i][j][1] + b1);
            float e10 = __expf(c[i][j][2] + b0);
            float e11 = __expf(c[i][j][3] + b1);
            rs[i][0] += e00 + e01;
            rs[i][1] += e10 + e11;
            *(__half2*)&g_eh[(size_t)row0 * VOCAB + colBase + cl] =
                __floats2half2_rn(e00, e01);
            *(__half2*)&g_eh[(size_t)(row0 + 8) * VOCAB + colBase + cl] =
                __floats2half2_rn(e10, e11);
        }
    }
#pragma unroll
    for (int i = 0; i < 4; i++) {
#pragma unroll
        for (int h = 0; h < 2; h++) {
            rs[i][h] += __shfl_xor_sync(0xffffffffu, rs[i][h], 1);
            rs[i][h] += __shfl_xor_sync(0xffffffffu, rs[i][h], 2);
        }
        if (t == 0) {
            atomicAdd(&srow[wr * 64 + i * 16 + g], rs[i][0]);
            atomicAdd(&srow[wr * 64 + i * 16 + g + 8], rs[i][1]);
        }
    }
    __syncthreads();
    if (tid < 128)
        g_partial[(size_t)blockIdx.x * NROWS + rowBase + tid] = srow[tid];
}

// ---------------- reduce partials -> 1/rowsum ----------------
__global__ __launch_bounds__(256) void k_rowsum() {
    int row = blockIdx.x * 256 + threadIdx.x;
    float s = 0.f;
    for (int j = 0; j < NT; j++) s += g_partial[(size_t)j * NROWS + row];
    g_inv[row] = 1.f / s;
}

// ---------------- normalize: out = fp16(exp) * inv[row], streaming ----------
// one thread = 8 halves (16B read, 32B write). 32000 % 8 == 0 -> single row.
__global__ __launch_bounds__(256) void k_norm(float* __restrict__ out) {
    size_t i8 = (size_t)blockIdx.x * 256 + threadIdx.x;
    int row = (int)(i8 / (VOCAB / 8));
    float inv = g_inv[row];
    const uint4 v = *(const uint4*)(g_eh + i8 * 8);
    const __half2* h = (const __half2*)&v;
    float4 o0, o1;
    float2 f;
    f = __half22float2(h[0]); o0.x = f.x * inv; o0.y = f.y * inv;
    f = __half22float2(h[1]); o0.z = f.x * inv; o0.w = f.y * inv;
    f = __half22float2(h[2]); o1.x = f.x * inv; o1.y = f.y * inv;
    f = __half22float2(h[3]); o1.z = f.x * inv; o1.w = f.y * inv;
    float4* op = (float4*)(out + i8 * 8);
    op[0] = o0;
    op[1] = o1;
}

// ---------------- launch ----------------
extern "C" void kernel_launch(void* const* d_in, const int* in_sizes, int n_in,
                              void* d_out, int out_size) {
    const float* enc = (const float*)d_in[0];
    const int*   dec = (const int*)d_in[1];
    const float* h0  = (const float*)d_in[2];
    const float* c0  = (const float*)d_in[3];
    const float* emb = (const float*)d_in[4];
    const float* Wx  = (const float*)d_in[5];
    const float* Wh  = (const float*)d_in[6];
    const float* bv  = (const float*)d_in[7];
    const float* Wd  = (const float*)d_in[8];
    const float* bd  = (const float*)d_in[9];
    float* out = (float*)d_out;

    cudaFuncSetAttribute(k_mma, cudaFuncAttributeMaxDynamicSharedMemorySize,
                         SMEM_MMA);

    k_cvtWd<<<dim3(VOCAB / 32, 4), 256>>>(Wd);
    k_xz<<<256, 256>>>(dec, emb, Wx, bv);
    k_lstm<<<NB, 256>>>(h0, c0, Wh, out + (size_t)NROWS * VOCAB);
    k_attn<<<dim3(TT / 16, NB), 256>>>(enc, h0);
    k_mma<<<dim3(NT, NROWS / BM), 256, SMEM_MMA>>>(bd);
    k_rowsum<<<NROWS / 256, 256>>>();
    k_norm<<<(NROWS * (VOCAB / 8)) / 256, 256>>>(out);
}